// round 2
// baseline (speedup 1.0000x reference)
#include <cuda_runtime.h>
#include <cstdint>
#include <math.h>

// ---------------- scratch offsets (floats) ----------------
#define OFF_WORDS 0ull
#define OFF_XG0F  (OFF_WORDS + 4096ull*125)
#define OFF_XG0B  (OFF_XG0F + 4096ull*500)
#define OFF_XG1F  (OFF_XG0B + 4096ull*500)
#define OFF_XG1B  (OFF_XG1F + 4096ull*500)
#define OFF_H0    (OFF_XG1B + 4096ull*500)
#define OFF_WE1   (OFF_H0   + 4096ull*250)
#define OFF_WH    (OFF_WE1  + 4096ull*250)
#define OFF_WM    (OFF_WH   + 4096ull*100)
#define OFF_RELM  (OFF_WM   + 4096ull*100)
#define OFF_RELH  (OFF_RELM + 4096ull*100)
#define SCR_TOT   (OFF_RELH + 4096ull*100)

__device__ float g_scr[SCR_TOT];
__device__ int   g_tree[4096];
__device__ int   g_gidx[4096];

// ---------------- prep: tree (col0 -> 0) + gather indices ----------------
__global__ void k_prep(const int* __restrict__ tarc) {
    int m = blockIdx.x * blockDim.x + threadIdx.x;
    if (m < 4096) {
        int v = ((m & 127) == 0) ? 0 : tarc[m];
        g_tree[m] = v;
        g_gidx[m] = (m >> 7) * 128 + v;
    }
}

// ---------------- embedding gather: words[4096,125] ----------------
__global__ void k_embed(const int* __restrict__ wid, const int* __restrict__ uid,
                        const float* __restrict__ wl, const float* __restrict__ tl) {
    int m = blockIdx.x;
    int t = threadIdx.x;
    float* w = g_scr + OFF_WORDS + (size_t)m * 125;
    if (t < 100)       w[t] = wl[(size_t)wid[m] * 100 + t];
    else if (t < 125)  w[t] = tl[(size_t)uid[m] * 25 + (t - 100)];
}

// ---------------- generic GEMM: C[4096,N] = A[4096,K] @ W[N,K]^T + bias ----------------
// BM=64, BN=64, BK=25 (divides 125/250/100). 256 threads, 4x4 microtile.
__global__ void __launch_bounds__(256) k_gemm(const float* __restrict__ A,
                                              const float* __restrict__ W,
                                              const float* __restrict__ bias,
                                              float* __restrict__ C,
                                              int N, int K,
                                              const int* __restrict__ gidx) {
    __shared__ __align__(16) float As[25][68];
    __shared__ __align__(16) float Ws[25][68];
    int t  = threadIdx.x;
    int tx = t & 15, ty = t >> 4;
    int m0 = blockIdx.y * 64, n0 = blockIdx.x * 64;
    float acc[4][4];
#pragma unroll
    for (int i = 0; i < 4; i++)
#pragma unroll
        for (int j = 0; j < 4; j++) acc[i][j] = 0.f;

    for (int k0 = 0; k0 < K; k0 += 25) {
        for (int i = t; i < 1600; i += 256) {
            int r = i / 25, kk = i - r * 25;
            int gm = m0 + r;
            int row = gidx ? gidx[gm] : gm;
            As[kk][r] = A[(size_t)row * K + k0 + kk];
        }
        for (int i = t; i < 1600; i += 256) {
            int r = i / 25, kk = i - r * 25;
            int gn = n0 + r;
            Ws[kk][r] = (gn < N) ? W[(size_t)gn * K + k0 + kk] : 0.f;
        }
        __syncthreads();
#pragma unroll
        for (int k = 0; k < 25; k++) {
            float4 a = *(const float4*)&As[k][ty * 4];
            float4 w = *(const float4*)&Ws[k][tx * 4];
            float av[4] = {a.x, a.y, a.z, a.w};
            float wv[4] = {w.x, w.y, w.z, w.w};
#pragma unroll
            for (int i = 0; i < 4; i++)
#pragma unroll
                for (int j = 0; j < 4; j++)
                    acc[i][j] = fmaf(av[i], wv[j], acc[i][j]);
        }
        __syncthreads();
    }
#pragma unroll
    for (int i = 0; i < 4; i++) {
        int row = m0 + ty * 4 + i;
#pragma unroll
        for (int j = 0; j < 4; j++) {
            int gn = n0 + tx * 4 + j;
            if (gn < N) C[(size_t)row * N + gn] = acc[i][j] + bias[gn];
        }
    }
}

// ---------------- cluster helpers ----------------
__device__ __forceinline__ void cluster_sync_() {
    asm volatile("barrier.cluster.arrive.aligned;" ::: "memory");
    asm volatile("barrier.cluster.wait.aligned;" ::: "memory");
}
__device__ __forceinline__ void st_peer(float* p, uint32_t peer, float v) {
    uint32_t la = (uint32_t)__cvta_generic_to_shared(p);
    uint32_t ra;
    asm volatile("mapa.shared::cluster.u32 %0, %1, %2;" : "=r"(ra) : "r"(la), "r"(peer));
    asm volatile("st.shared::cluster.f32 [%0], %1;" :: "r"(ra), "f"(v) : "memory");
}

// ---------------- LSTM scan: 64 (b,dir) pairs x 2-CTA clusters ----------------
// CTA rank 0: cells [0,63), rank 1: cells [63,125). Thread t: q=t>>6 (gate),
// jj=t&63 (cell). Each thread holds one 125-wide Whh gate row in registers.
__global__ void __cluster_dims__(2,1,1) __launch_bounds__(256, 1)
k_scan(const float* __restrict__ xgf, const float* __restrict__ xgb,
       const float* __restrict__ whf, const float* __restrict__ whb,
       float* __restrict__ hout) {
    __shared__ __align__(16) float hs[2][128];
    __shared__ float gacc[256];
    int cta = blockIdx.x;
    uint32_t r = cta & 1;
    int p = cta >> 1;
    int b = p & 31, dir = p >> 5;
    const float* xg  = dir ? xgb : xgf;
    const float* Whh = dir ? whb : whf;
    int jbase = r ? 63 : 0;
    int cnt   = r ? 62 : 63;
    int t  = threadIdx.x;
    int q  = t >> 6, jj = t & 63;
    bool act = jj < cnt;
    int grow = q * 125 + jbase + jj;

    float w[128];
#pragma unroll
    for (int k = 0; k < 125; k++) w[k] = act ? Whh[grow * 125 + k] : 0.f;
    w[125] = 0.f; w[126] = 0.f; w[127] = 0.f;

    if (t < 128) { hs[0][t] = 0.f; hs[1][t] = 0.f; }
    float c = 0.f;
    cluster_sync_();

    int par = 0;
    const size_t brow = (size_t)b * 128;
    for (int s = 0; s < 128; s++) {
        int tt = dir ? (127 - s) : s;
        float xv = act ? xg[(brow + tt) * 500 + grow] : 0.f;
        const float4* h4 = (const float4*)hs[par];
        float a0 = 0.f, a1 = 0.f, a2 = 0.f, a3 = 0.f;
#pragma unroll
        for (int k4 = 0; k4 < 32; k4++) {
            float4 hv = h4[k4];
            a0 = fmaf(hv.x, w[4 * k4 + 0], a0);
            a1 = fmaf(hv.y, w[4 * k4 + 1], a1);
            a2 = fmaf(hv.z, w[4 * k4 + 2], a2);
            a3 = fmaf(hv.w, w[4 * k4 + 3], a3);
        }
        gacc[t] = ((a0 + a1) + (a2 + a3)) + xv;
        __syncthreads();
        if (q == 0 && act) {
            float gi = gacc[jj], gf = gacc[64 + jj], gg = gacc[128 + jj], go = gacc[192 + jj];
            float si = 1.f / (1.f + expf(-gi));
            float sf = 1.f / (1.f + expf(-gf));
            float so = 1.f / (1.f + expf(-go));
            c = sf * c + si * tanhf(gg);
            float h = so * tanhf(c);
            int j = jbase + jj;
            float* dst = &hs[par ^ 1][j];
            *dst = h;
            st_peer(dst, r ^ 1u, h);
            hout[(brow + tt) * 250 + dir * 125 + j] = h;
        }
        cluster_sync_();
        par ^= 1;
    }
}

// ---------------- biaffine arc scores + margin + argmax ----------------
// score[b,i,j] = es_b + 1 - [j==tree] + sum_h esW[h]*tanh(wh[b,i,h]+wm[b,j,h])
// tanh(x) = 1 - 2/(1+e^{2x}); inputs prescaled by 2*log2(e) so e^{2x}=2^(a+b).
__global__ void __launch_bounds__(256) k_arc(const float* __restrict__ esW,
                                             const float* __restrict__ esb,
                                             float* __restrict__ arc_out,
                                             float* __restrict__ parsed_out) {
    extern __shared__ float sm[];
    float* wms   = sm;                 // 128*101
    float* whs   = sm + 128 * 101;     // 16*101
    float* esw   = whs + 16 * 101;     // 100
    float* baseS = esw + 100;          // 1
    int*   treei = (int*)(baseS + 1);  // 16
    const float S = 2.885390081777927f; // 2*log2(e)
    int b = blockIdx.y, i0 = blockIdx.x * 16;
    int t = threadIdx.x;
    const float* wm = g_scr + OFF_WM + (size_t)b * 128 * 100;
    const float* wh = g_scr + OFF_WH + ((size_t)b * 128 + i0) * 100;
    for (int idx = t; idx < 12800; idx += 256) {
        int j = idx / 100, h = idx - j * 100;
        wms[j * 101 + h] = wm[j * 100 + h] * S;
    }
    for (int idx = t; idx < 1600; idx += 256) {
        int ii = idx / 100, h = idx - ii * 100;
        whs[ii * 101 + h] = wh[ii * 100 + h] * S;
    }
    if (t < 100) esw[t] = -2.f * esW[t];
    if (t == 0) {
        float ssum = 0.f;
        for (int h = 0; h < 100; h++) ssum += esW[h];
        baseS[0] = ssum + esb[0] + 1.f;
    }
    if (t < 16) treei[t] = g_tree[b * 128 + i0 + t];
    __syncthreads();

    int ii = t >> 4, jl = t & 15;
    int i = i0 + ii;
    int tgt = treei[ii];
    float base = baseS[0];
    float best = -1e30f; int bj = 0;
    float* arow = g_scr ? arc_out + ((size_t)b * 128 + i) * 128 : arc_out;
    const float* Arow = whs + ii * 101;
    for (int jt = 0; jt < 8; jt++) {
        int j = jl + 16 * jt;
        const float* Brow = wms + j * 101;
        float acc = 0.f;
#pragma unroll
        for (int h = 0; h < 100; h++) {
            float x = Arow[h] + Brow[h];
            float e; asm("ex2.approx.f32 %0, %1;" : "=f"(e) : "f"(x));
            float d = 1.f + e;
            float rr; asm("rcp.approx.f32 %0, %1;" : "=f"(rr) : "f"(d));
            acc = fmaf(esw[h], rr, acc);
        }
        float sc = base + acc - ((j == tgt) ? 1.f : 0.f);
        arow[j] = sc;
        if (sc > best) { best = sc; bj = j; }
    }
    // reduce across the 16 lanes sharing ii (xor offsets < 16 stay in-group)
    for (int off = 8; off; off >>= 1) {
        float ob = __shfl_xor_sync(0xffffffffu, best, off);
        int   oj = __shfl_xor_sync(0xffffffffu, bj, off);
        if (ob > best || (ob == best && oj < bj)) { best = ob; bj = oj; }
    }
    if (jl == 0) parsed_out[b * 128 + i] = (float)bj;
}

// ---------------- rel scores + argmax ----------------
__global__ void k_rel(const float* __restrict__ lsW, const float* __restrict__ lsb,
                      float* __restrict__ rel_out, float* __restrict__ pred_out) {
    __shared__ float th[100];
    __shared__ float sc[50];
    int m = blockIdx.x, t = threadIdx.x;
    const float* rm = g_scr + OFF_RELM + (size_t)m * 100;
    const float* rh = g_scr + OFF_RELH + (size_t)m * 100;
    for (int h = t; h < 100; h += 64) th[h] = tanhf(rm[h] + rh[h]);
    __syncthreads();
    if (t < 50) {
        float acc = lsb[t];
        const float* wr = lsW + t * 100;
#pragma unroll 10
        for (int h = 0; h < 100; h++) acc = fmaf(th[h], wr[h], acc);
        rel_out[(size_t)m * 50 + t] = acc;
        sc[t] = acc;
    }
    __syncthreads();
    if (t == 0) {
        float best = sc[0]; int bl = 0;
        for (int l = 1; l < 50; l++) if (sc[l] > best) { best = sc[l]; bl = l; }
        pred_out[m] = (float)bl;
    }
}

// ---------------- launch ----------------
extern "C" void kernel_launch(void* const* d_in, const int* in_sizes, int n_in,
                              void* d_out, int out_size) {
    const int* wid  = (const int*)d_in[0];
    const int* uid  = (const int*)d_in[1];
    const int* tarc = (const int*)d_in[2];
    const float* wl = (const float*)d_in[3];
    const float* tl = (const float*)d_in[4];
    const float* l0f_Wih = (const float*)d_in[5];
    const float* l0f_Whh = (const float*)d_in[6];
    const float* l0f_b   = (const float*)d_in[7];
    const float* l0b_Wih = (const float*)d_in[8];
    const float* l0b_Whh = (const float*)d_in[9];
    const float* l0b_b   = (const float*)d_in[10];
    const float* l1f_Wih = (const float*)d_in[11];
    const float* l1f_Whh = (const float*)d_in[12];
    const float* l1f_b   = (const float*)d_in[13];
    const float* l1b_Wih = (const float*)d_in[14];
    const float* l1b_Whh = (const float*)d_in[15];
    const float* l1b_b   = (const float*)d_in[16];
    const float* ehW = (const float*)d_in[17];
    const float* ehb = (const float*)d_in[18];
    const float* emW = (const float*)d_in[19];
    const float* emb = (const float*)d_in[20];
    const float* esW = (const float*)d_in[21];
    const float* esb = (const float*)d_in[22];
    const float* lhW = (const float*)d_in[23];
    const float* lhb = (const float*)d_in[24];
    const float* lmW = (const float*)d_in[25];
    const float* lmb = (const float*)d_in[26];
    const float* lsW = (const float*)d_in[27];
    const float* lsb = (const float*)d_in[28];
    float* out = (float*)d_out;

    float* scr = nullptr;
    cudaGetSymbolAddress((void**)&scr, g_scr);
    int* gidxp = nullptr;
    cudaGetSymbolAddress((void**)&gidxp, g_gidx);
    float* WORDS = scr + OFF_WORDS;
    float* XG0F = scr + OFF_XG0F;
    float* XG0B = scr + OFF_XG0B;
    float* XG1F = scr + OFF_XG1F;
    float* XG1B = scr + OFF_XG1B;
    float* H0   = scr + OFF_H0;
    float* WE1  = scr + OFF_WE1;
    float* WH   = scr + OFF_WH;
    float* WM   = scr + OFF_WM;
    float* RELM = scr + OFF_RELM;
    float* RELH = scr + OFF_RELH;

    k_prep<<<16, 256>>>(tarc);
    k_embed<<<4096, 128>>>(wid, uid, wl, tl);

    dim3 thr(256);
    dim3 g500(8, 64), g100(2, 64);
    k_gemm<<<g500, thr>>>(WORDS, l0f_Wih, l0f_b, XG0F, 500, 125, nullptr);
    k_gemm<<<g500, thr>>>(WORDS, l0b_Wih, l0b_b, XG0B, 500, 125, nullptr);
    k_scan<<<128, 256>>>(XG0F, XG0B, l0f_Whh, l0b_Whh, H0);
    k_gemm<<<g500, thr>>>(H0, l1f_Wih, l1f_b, XG1F, 500, 250, nullptr);
    k_gemm<<<g500, thr>>>(H0, l1b_Wih, l1b_b, XG1B, 500, 250, nullptr);
    k_scan<<<128, 256>>>(XG1F, XG1B, l1f_Whh, l1b_Whh, WE1);
    k_gemm<<<g100, thr>>>(WE1, ehW, ehb, WH,   100, 250, nullptr);
    k_gemm<<<g100, thr>>>(WE1, emW, emb, WM,   100, 250, nullptr);
    k_gemm<<<g100, thr>>>(WE1, lmW, lmb, RELM, 100, 250, nullptr);
    k_gemm<<<g100, thr>>>(WE1, lhW, lhb, RELH, 100, 250, gidxp);

    cudaFuncSetAttribute(k_arc, cudaFuncAttributeMaxDynamicSharedMemorySize, 60000);
    k_arc<<<dim3(8, 32), 256, 58656>>>(esW, esb, out + 8192, out);
    k_rel<<<4096, 64>>>(lsW, lsb, out + 532480, out + 4096);
}

// round 3
// speedup vs baseline: 1.3752x; 1.3752x over previous
#include <cuda_runtime.h>
#include <cstdint>
#include <math.h>

typedef unsigned long long ULL;

// ---------------- scratch offsets (floats) ----------------
#define OFF_WORDS 0ull                               // 4096*128
#define OFF_XG0F (OFF_WORDS + 524288ull)             // 4096*500
#define OFF_XG0B (OFF_XG0F + 2048000ull)
#define OFF_XG1F (OFF_XG0B + 2048000ull)
#define OFF_XG1B (OFF_XG1F + 2048000ull)
#define OFF_H0   (OFF_XG1B + 2048000ull)             // 4096*256
#define OFF_WE1  (OFF_H0   + 1048576ull)             // 4096*256
#define OFF_SCOR (OFF_WE1  + 1048576ull)             // 4096*400
#define OFF_WIH0 (OFF_SCOR + 1638400ull)             // 2*512*128
#define OFF_WIH1 (OFF_WIH0 + 131072ull)              // 2*512*256
#define OFF_SW   (OFF_WIH1 + 262144ull)              // 448*256
#define OFF_B0   (OFF_SW   + 114688ull)              // 2*512
#define OFF_B1   (OFF_B0   + 1024ull)                // 2*512
#define OFF_SB   (OFF_B1   + 1024ull)                // 448
#define SCR_TOT  (OFF_SB   + 448ull)

__device__ float g_scr[SCR_TOT];
__device__ int   g_tree[4096];
__device__ int   g_gidx[4096];

// ---------------- f32x2 helpers ----------------
__device__ __forceinline__ ULL pk2(float x, float y) {
    ULL r; asm("mov.b64 %0,{%1,%2};" : "=l"(r) : "f"(x), "f"(y)); return r;
}
__device__ __forceinline__ float2 upk2(ULL v) {
    float2 r; asm("mov.b64 {%0,%1},%2;" : "=f"(r.x), "=f"(r.y) : "l"(v)); return r;
}
__device__ __forceinline__ void fma2(ULL& c, ULL a, ULL b) {
    asm("fma.rn.f32x2 %0,%1,%2,%0;" : "+l"(c) : "l"(a), "l"(b));
}
__device__ __forceinline__ float sig_f(float x) {
    x = fminf(15.f, fmaxf(-15.f, x));
    float e; asm("ex2.approx.f32 %0,%1;" : "=f"(e) : "f"(-1.4426950408889634f * x));
    float r; asm("rcp.approx.f32 %0,%1;" : "=f"(r) : "f"(1.f + e));
    return r;
}
__device__ __forceinline__ float tanh_f(float x) {
    x = fminf(15.f, fmaxf(-15.f, x));
    float e; asm("ex2.approx.f32 %0,%1;" : "=f"(e) : "f"(2.885390081777927f * x));
    float r; asm("rcp.approx.f32 %0,%1;" : "=f"(r) : "f"(e + 1.f));
    return (e - 1.f) * r;
}
__device__ __forceinline__ uint32_t sa(const void* p) {
    return (uint32_t)__cvta_generic_to_shared(p);
}
__device__ __forceinline__ void cluster_sync_() {
    asm volatile("barrier.cluster.arrive.aligned;" ::: "memory");
    asm volatile("barrier.cluster.wait.aligned;" ::: "memory");
}

// ---------------- prep: pack/pad weights, biases, tree/gidx, zero pads ----------------
__global__ void k_prep(const int* __restrict__ tarc,
                       const float* __restrict__ l0fW, const float* __restrict__ l0bW,
                       const float* __restrict__ l1fW, const float* __restrict__ l1bW,
                       const float* __restrict__ ehW, const float* __restrict__ emW,
                       const float* __restrict__ lmW, const float* __restrict__ lhW,
                       const float* __restrict__ l0fb, const float* __restrict__ l0bb,
                       const float* __restrict__ l1fb, const float* __restrict__ l1bb,
                       const float* __restrict__ ehb, const float* __restrict__ emb,
                       const float* __restrict__ lmb, const float* __restrict__ lhb) {
    int idx = blockIdx.x * 256 + threadIdx.x;
    const int E0 = 131072, E1 = E0 + 262144, E2 = E1 + 114688, E3 = E2 + 1024,
              E4 = E3 + 1024, E5 = E4 + 448, E6 = E5 + 4096, E7 = E6 + 24576, E8 = E7 + 24576;
    if (idx < E0) {                       // WIH0 [2][512][128]
        int z = idx >> 16, r = idx & 65535, n = r >> 7, k = r & 127;
        const float* s = z ? l0bW : l0fW;
        g_scr[OFF_WIH0 + idx] = (n < 500 && k < 125) ? s[n * 125 + k] : 0.f;
    } else if (idx < E1) {                // WIH1 [2][512][256]
        int i = idx - E0, z = i >> 17, r = i & 131071, n = r >> 8, k = r & 255;
        const float* s = z ? l1bW : l1fW;
        g_scr[OFF_WIH1 + i] = (n < 500 && k < 250) ? s[n * 250 + k] : 0.f;
    } else if (idx < E2) {                // SW [448][256]: eh,em,lm,lh each 100 rows
        int i = idx - E1, n = i >> 8, k = i & 255;
        float v = 0.f;
        if (k < 250 && n < 400) {
            int sel = n / 100, nn = n - sel * 100;
            const float* s = sel == 0 ? ehW : sel == 1 ? emW : sel == 2 ? lmW : lhW;
            v = s[nn * 250 + k];
        }
        g_scr[OFF_SW + i] = v;
    } else if (idx < E3) {                // B0 [2][512]
        int i = idx - E2, z = i >> 9, n = i & 511;
        g_scr[OFF_B0 + i] = (n < 500) ? (z ? l0bb[n] : l0fb[n]) : 0.f;
    } else if (idx < E4) {                // B1 [2][512]
        int i = idx - E3, z = i >> 9, n = i & 511;
        g_scr[OFF_B1 + i] = (n < 500) ? (z ? l1bb[n] : l1fb[n]) : 0.f;
    } else if (idx < E5) {                // SB [448]
        int n = idx - E4;
        float v = 0.f;
        if (n < 400) {
            int sel = n / 100, nn = n - sel * 100;
            v = sel == 0 ? ehb[nn] : sel == 1 ? emb[nn] : sel == 2 ? lmb[nn] : lhb[nn];
        }
        g_scr[OFF_SB + n] = v;
    } else if (idx < E6) {                // tree + gidx
        int m = idx - E5;
        int v = ((m & 127) == 0) ? 0 : tarc[m];
        g_tree[m] = v;
        g_gidx[m] = (m >> 7) * 128 + v;
    } else if (idx < E7) {                // H0 pad cols 250..255
        int i = idx - E6, m = i / 6, c = i - m * 6;
        g_scr[OFF_H0 + (size_t)m * 256 + 250 + c] = 0.f;
    } else if (idx < E8) {                // WE1 pad cols
        int i = idx - E7, m = i / 6, c = i - m * 6;
        g_scr[OFF_WE1 + (size_t)m * 256 + 250 + c] = 0.f;
    }
}

// ---------------- embedding gather: words[4096,128] (padded) ----------------
__global__ void k_embed(const int* __restrict__ wid, const int* __restrict__ uid,
                        const float* __restrict__ wl, const float* __restrict__ tl) {
    int m = blockIdx.x, t = threadIdx.x;
    float* w = g_scr + OFF_WORDS + (size_t)m * 128;
    float v = 0.f;
    if (t < 100)      v = wl[(size_t)wid[m] * 100 + t];
    else if (t < 125) v = tl[(size_t)uid[m] * 25 + (t - 100)];
    w[t] = v;
}

// ---------------- GEMM: C[z][4096,N] = A[4096,K] @ Wp[z][Npad,K]^T + Bp[z] ----------------
// BM=64 BN=64 BK=32, 256 thr, 4x4 microtile, m-paired f32x2.
__global__ void __launch_bounds__(256) k_gemm(const float* __restrict__ A,
                                              const float* __restrict__ Wp,
                                              const float* __restrict__ Bp,
                                              float* __restrict__ C,
                                              int N, int K, int ldWz, int bstride,
                                              long long zsC) {
    __shared__ __align__(16) float As[32][68];
    __shared__ __align__(16) float Ws[32][68];
    int z = blockIdx.z;
    const float* Wz = Wp + (size_t)z * ldWz;
    const float* bz = Bp + (size_t)z * bstride;
    float* Cz = C + (size_t)z * zsC;
    int t = threadIdx.x, tx = t & 15, ty = t >> 4;
    int m0 = blockIdx.y * 64, n0 = blockIdx.x * 64;
    int mf = t >> 3, kg = t & 7;          // fill coords (row 0..31, kgroup 0..7)

    ULL acc[2][4];
#pragma unroll
    for (int i = 0; i < 2; i++)
#pragma unroll
        for (int j = 0; j < 4; j++) acc[i][j] = 0ull;

    uint32_t aAddr = sa(&As[0][ty * 4]);
    uint32_t wAddr = sa(&Ws[0][tx * 4]);

    for (int k0 = 0; k0 < K; k0 += 32) {
        float4 av1 = *(const float4*)(A  + (size_t)(m0 + mf) * K + k0 + kg * 4);
        float4 av2 = *(const float4*)(A  + (size_t)(m0 + mf + 32) * K + k0 + kg * 4);
        float4 wv1 = *(const float4*)(Wz + (size_t)(n0 + mf) * K + k0 + kg * 4);
        float4 wv2 = *(const float4*)(Wz + (size_t)(n0 + mf + 32) * K + k0 + kg * 4);
        As[kg * 4 + 0][mf] = av1.x; As[kg * 4 + 1][mf] = av1.y;
        As[kg * 4 + 2][mf] = av1.z; As[kg * 4 + 3][mf] = av1.w;
        As[kg * 4 + 0][mf + 32] = av2.x; As[kg * 4 + 1][mf + 32] = av2.y;
        As[kg * 4 + 2][mf + 32] = av2.z; As[kg * 4 + 3][mf + 32] = av2.w;
        Ws[kg * 4 + 0][mf] = wv1.x; Ws[kg * 4 + 1][mf] = wv1.y;
        Ws[kg * 4 + 2][mf] = wv1.z; Ws[kg * 4 + 3][mf] = wv1.w;
        Ws[kg * 4 + 0][mf + 32] = wv2.x; Ws[kg * 4 + 1][mf + 32] = wv2.y;
        Ws[kg * 4 + 2][mf + 32] = wv2.z; Ws[kg * 4 + 3][mf + 32] = wv2.w;
        __syncthreads();
#pragma unroll
        for (int k = 0; k < 32; k++) {
            ULL a01, a23;
            asm volatile("ld.shared.v2.u64 {%0,%1},[%2];"
                         : "=l"(a01), "=l"(a23) : "r"(aAddr + k * 272));
            float4 wv = *(const float4*)&Ws[k][tx * 4];
            ULL w0 = pk2(wv.x, wv.x), w1 = pk2(wv.y, wv.y);
            ULL w2 = pk2(wv.z, wv.z), w3 = pk2(wv.w, wv.w);
            fma2(acc[0][0], a01, w0); fma2(acc[1][0], a23, w0);
            fma2(acc[0][1], a01, w1); fma2(acc[1][1], a23, w1);
            fma2(acc[0][2], a01, w2); fma2(acc[1][2], a23, w2);
            fma2(acc[0][3], a01, w3); fma2(acc[1][3], a23, w3);
        }
        __syncthreads();
    }
    int n = n0 + tx * 4;
    float b0 = (n     < N) ? bz[n]     : 0.f;
    float b1 = (n + 1 < N) ? bz[n + 1] : 0.f;
    float b2 = (n + 2 < N) ? bz[n + 2] : 0.f;
    float b3 = (n + 3 < N) ? bz[n + 3] : 0.f;
#pragma unroll
    for (int i = 0; i < 2; i++) {
        float2 t0 = upk2(acc[i][0]), t1 = upk2(acc[i][1]);
        float2 t2 = upk2(acc[i][2]), t3 = upk2(acc[i][3]);
#pragma unroll
        for (int rr = 0; rr < 2; rr++) {
            int m = m0 + ty * 4 + i * 2 + rr;
            float4 v = rr ? make_float4(t0.y + b0, t1.y + b1, t2.y + b2, t3.y + b3)
                          : make_float4(t0.x + b0, t1.x + b1, t2.x + b2, t3.x + b3);
            if (n + 3 < N) {
                *(float4*)(Cz + (size_t)m * N + n) = v;
            } else {
                float vv[4] = {v.x, v.y, v.z, v.w};
                for (int jj = 0; jj < 4; jj++)
                    if (n + jj < N) Cz[(size_t)m * N + n + jj] = vv[jj];
            }
        }
    }
}

// ---------------- LSTM scan: 64 (b,dir) x 2-CTA clusters, mbarrier sync ----------------
__global__ void __cluster_dims__(2, 1, 1) __launch_bounds__(256, 1)
k_scan(const float* __restrict__ xgf, const float* __restrict__ xgb,
       const float* __restrict__ whf, const float* __restrict__ whb,
       float* __restrict__ hout) {
    __shared__ __align__(16) float hs[2][128];
    __shared__ float sact[256];
    __shared__ __align__(8) unsigned long long mbar;
    int cta = blockIdx.x;
    uint32_t rk = cta & 1;
    int p = cta >> 1, b = p & 31, dir = p >> 5;
    const float* xg  = dir ? xgb : xgf;
    const float* Whh = dir ? whb : whf;
    int jbase = rk ? 63 : 0, cnt = rk ? 62 : 63;
    int t = threadIdx.x, q = t >> 6, jj = t & 63;
    bool act = jj < cnt;
    int grow = act ? (q * 125 + jbase + jj) : 0;

    ULL wreg[64];
    const float* wrow = Whh + (size_t)grow * 125;
#pragma unroll
    for (int kk = 0; kk < 64; kk++) {
        float w0 = (act && 2 * kk < 125)     ? wrow[2 * kk]     : 0.f;
        float w1 = (act && 2 * kk + 1 < 125) ? wrow[2 * kk + 1] : 0.f;
        wreg[kk] = pk2(w0, w1);
    }
    if (t < 128) { hs[0][t] = 0.f; hs[1][t] = 0.f; }
    uint32_t mb = sa(&mbar);
    if (t == 0)
        asm volatile("mbarrier.init.shared.b64 [%0], %1;" :: "r"(mb), "r"(2u) : "memory");
    cluster_sync_();

    uint32_t hsb = sa(&hs[0][0]);
    uint32_t rhsb, rmb;
    asm("mapa.shared::cluster.u32 %0,%1,%2;" : "=r"(rhsb) : "r"(hsb), "r"(rk ^ 1u));
    asm("mapa.shared::cluster.u32 %0,%1,%2;" : "=r"(rmb)  : "r"(mb),  "r"(rk ^ 1u));

    float c = 0.f;
    int par = 0;
    uint32_t ph = 0;
    const size_t brow = (size_t)b * 128;
    int tt0 = dir ? 127 : 0;
    float xv = act ? xg[(brow + tt0) * 500 + grow] : 0.f;

    for (int s = 0; s < 128; s++) {
        int tt = dir ? (127 - s) : s;
        ULL a0 = 0ull, a1 = 0ull, a2 = 0ull, a3 = 0ull;
        uint32_t hb = hsb + par * 512;
#pragma unroll
        for (int kk = 0; kk < 32; kk++) {
            ULL h01, h23;
            asm volatile("ld.shared.v2.u64 {%0,%1},[%2];"
                         : "=l"(h01), "=l"(h23) : "r"(hb + kk * 16));
            if (kk & 1) { fma2(a2, h01, wreg[2 * kk]); fma2(a3, h23, wreg[2 * kk + 1]); }
            else        { fma2(a0, h01, wreg[2 * kk]); fma2(a1, h23, wreg[2 * kk + 1]); }
        }
        float2 f0 = upk2(a0), f1 = upk2(a1), f2 = upk2(a2), f3 = upk2(a3);
        float g = ((f0.x + f0.y) + (f1.x + f1.y)) + ((f2.x + f2.y) + (f3.x + f3.y)) + xv;
        if (s + 1 < 128) {
            int tn = dir ? (126 - s) : (s + 1);
            xv = act ? xg[(brow + tn) * 500 + grow] : 0.f;
        }
        sact[t] = (q == 2) ? tanh_f(g) : sig_f(g);
        __syncthreads();
        if (q == 0 && act) {
            float si = sact[jj], sf = sact[64 + jj], tg = sact[128 + jj], so = sact[192 + jj];
            c = sf * c + si * tg;
            float h = so * tanh_f(c);
            int j = jbase + jj;
            hs[par ^ 1][j] = h;
            asm volatile("st.shared::cluster.f32 [%0],%1;"
                         :: "r"(rhsb + (par ^ 1) * 512 + j * 4), "f"(h) : "memory");
            hout[(brow + tt) * 256 + dir * 125 + j] = h;
        }
        __syncthreads();
        if (t == 0) {
            asm volatile("mbarrier.arrive.release.cluster.shared::cta.b64 _,[%0];"
                         :: "r"(mb) : "memory");
            asm volatile("mbarrier.arrive.release.cluster.shared::cluster.b64 _,[%0];"
                         :: "r"(rmb) : "memory");
        }
        uint32_t done;
        do {
            asm volatile("{\n\t.reg .pred P;\n\t"
                         "mbarrier.try_wait.parity.acquire.cluster.shared::cta.b64 P,[%1],%2;\n\t"
                         "selp.b32 %0,1,0,P;\n\t}"
                         : "=r"(done) : "r"(mb), "r"(ph) : "memory");
        } while (!done);
        ph ^= 1;
        par ^= 1;
    }
    cluster_sync_();
}

// ---------------- biaffine arc scores + margin + argmax ----------------
__global__ void __launch_bounds__(256) k_arc(const float* __restrict__ esW,
                                             const float* __restrict__ esb,
                                             float* __restrict__ arc_out,
                                             float* __restrict__ parsed_out) {
    extern __shared__ float sm[];
    float* wms   = sm;                 // 128*101
    float* whs   = sm + 128 * 101;     // 16*101
    float* esw   = whs + 16 * 101;     // 100
    float* baseS = esw + 100;          // 1
    int*   treei = (int*)(baseS + 1);  // 16
    const float S = 2.885390081777927f; // 2*log2(e)
    int b = blockIdx.y, i0 = blockIdx.x * 16;
    int t = threadIdx.x;
    const float* wm = g_scr + OFF_SCOR + (size_t)b * 128 * 400 + 100;
    const float* wh = g_scr + OFF_SCOR + ((size_t)b * 128 + i0) * 400;
    for (int idx = t; idx < 12800; idx += 256) {
        int j = idx / 100, h = idx - j * 100;
        wms[j * 101 + h] = wm[(size_t)j * 400 + h] * S;
    }
    for (int idx = t; idx < 1600; idx += 256) {
        int ii = idx / 100, h = idx - ii * 100;
        whs[ii * 101 + h] = wh[(size_t)ii * 400 + h] * S;
    }
    if (t < 100) esw[t] = -2.f * esW[t];
    if (t == 0) {
        float ssum = 0.f;
        for (int h = 0; h < 100; h++) ssum += esW[h];
        baseS[0] = ssum + esb[0] + 1.f;
    }
    if (t < 16) treei[t] = g_tree[b * 128 + i0 + t];
    __syncthreads();

    int ii = t >> 4, jl = t & 15;
    int i = i0 + ii;
    int tgt = treei[ii];
    float base = baseS[0];
    float best = -1e30f; int bj = 0;
    float* arow = arc_out + ((size_t)b * 128 + i) * 128;
    const float* Arow = whs + ii * 101;
    for (int jt = 0; jt < 8; jt++) {
        int j = jl + 16 * jt;
        const float* Brow = wms + j * 101;
        float acc = 0.f;
#pragma unroll
        for (int h = 0; h < 100; h++) {
            float x = Arow[h] + Brow[h];
            float e; asm("ex2.approx.f32 %0, %1;" : "=f"(e) : "f"(x));
            float rr; asm("rcp.approx.f32 %0, %1;" : "=f"(rr) : "f"(1.f + e));
            acc = fmaf(esw[h], rr, acc);
        }
        float sc = base + acc - ((j == tgt) ? 1.f : 0.f);
        arow[j] = sc;
        if (sc > best) { best = sc; bj = j; }
    }
    for (int off = 8; off; off >>= 1) {
        float ob = __shfl_xor_sync(0xffffffffu, best, off);
        int   oj = __shfl_xor_sync(0xffffffffu, bj, off);
        if (ob > best || (ob == best && oj < bj)) { best = ob; bj = oj; }
    }
    if (jl == 0) parsed_out[b * 128 + i] = (float)bj;
}

// ---------------- rel scores + argmax (head gather post-projection) ----------------
__global__ void k_rel(const float* __restrict__ lsW, const float* __restrict__ lsb,
                      float* __restrict__ rel_out, float* __restrict__ pred_out) {
    __shared__ float th[100];
    __shared__ float sc[50];
    int m = blockIdx.x, t = threadIdx.x;
    const float* rm = g_scr + OFF_SCOR + (size_t)m * 400 + 200;
    const float* rh = g_scr + OFF_SCOR + (size_t)g_gidx[m] * 400 + 300;
    for (int h = t; h < 100; h += 64) th[h] = tanhf(rm[h] + rh[h]);
    __syncthreads();
    if (t < 50) {
        float acc = lsb[t];
        const float* wr = lsW + t * 100;
#pragma unroll 10
        for (int h = 0; h < 100; h++) acc = fmaf(th[h], wr[h], acc);
        rel_out[(size_t)m * 50 + t] = acc;
        sc[t] = acc;
    }
    __syncthreads();
    if (t == 0) {
        float best = sc[0]; int bl = 0;
        for (int l = 1; l < 50; l++) if (sc[l] > best) { best = sc[l]; bl = l; }
        pred_out[m] = (float)bl;
    }
}

// ---------------- launch ----------------
extern "C" void kernel_launch(void* const* d_in, const int* in_sizes, int n_in,
                              void* d_out, int out_size) {
    const int* wid  = (const int*)d_in[0];
    const int* uid  = (const int*)d_in[1];
    const int* tarc = (const int*)d_in[2];
    const float* wl = (const float*)d_in[3];
    const float* tl = (const float*)d_in[4];
    const float* l0f_Wih = (const float*)d_in[5];
    const float* l0f_Whh = (const float*)d_in[6];
    const float* l0f_b   = (const float*)d_in[7];
    const float* l0b_Wih = (const float*)d_in[8];
    const float* l0b_Whh = (const float*)d_in[9];
    const float* l0b_b   = (const float*)d_in[10];
    const float* l1f_Wih = (const float*)d_in[11];
    const float* l1f_Whh = (const float*)d_in[12];
    const float* l1f_b   = (const float*)d_in[13];
    const float* l1b_Wih = (const float*)d_in[14];
    const float* l1b_Whh = (const float*)d_in[15];
    const float* l1b_b   = (const float*)d_in[16];
    const float* ehW = (const float*)d_in[17];
    const float* ehb = (const float*)d_in[18];
    const float* emW = (const float*)d_in[19];
    const float* emb = (const float*)d_in[20];
    const float* esW = (const float*)d_in[21];
    const float* esb = (const float*)d_in[22];
    const float* lhW = (const float*)d_in[23];
    const float* lhb = (const float*)d_in[24];
    const float* lmW = (const float*)d_in[25];
    const float* lmb = (const float*)d_in[26];
    const float* lsW = (const float*)d_in[27];
    const float* lsb = (const float*)d_in[28];
    float* out = (float*)d_out;

    float* scr = nullptr;
    cudaGetSymbolAddress((void**)&scr, g_scr);
    float* WORDS = scr + OFF_WORDS;
    float* XG0F = scr + OFF_XG0F;
    float* XG0B = scr + OFF_XG0B;
    float* XG1F = scr + OFF_XG1F;
    float* XG1B = scr + OFF_XG1B;
    float* H0   = scr + OFF_H0;
    float* WE1  = scr + OFF_WE1;
    float* SCOR = scr + OFF_SCOR;
    float* WIH0 = scr + OFF_WIH0;
    float* WIH1 = scr + OFF_WIH1;
    float* SW   = scr + OFF_SW;
    float* B0   = scr + OFF_B0;
    float* B1   = scr + OFF_B1;
    float* SB   = scr + OFF_SB;

    k_prep<<<2202, 256>>>(tarc, l0f_Wih, l0b_Wih, l1f_Wih, l1b_Wih,
                          ehW, emW, lmW, lhW,
                          l0f_b, l0b_b, l1f_b, l1b_b, ehb, emb, lmb, lhb);
    k_embed<<<4096, 128>>>(wid, uid, wl, tl);

    k_gemm<<<dim3(8, 64, 2), 256>>>(WORDS, WIH0, B0, XG0F, 500, 128,
                                    512 * 128, 512, 2048000LL);
    k_scan<<<128, 256>>>(XG0F, XG0B, l0f_Whh, l0b_Whh, H0);
    k_gemm<<<dim3(8, 64, 2), 256>>>(H0, WIH1, B1, XG1F, 500, 256,
                                    512 * 256, 512, 2048000LL);
    k_scan<<<128, 256>>>(XG1F, XG1B, l1f_Whh, l1b_Whh, WE1);
    k_gemm<<<dim3(7, 64, 1), 256>>>(WE1, SW, SB, SCOR, 400, 256, 0, 0, 0LL);

    cudaFuncSetAttribute(k_arc, cudaFuncAttributeMaxDynamicSharedMemorySize, 60000);
    k_arc<<<dim3(8, 32), 256, 58656>>>(esW, esb, out + 8192, out);
    k_rel<<<4096, 64>>>(lsW, lsb, out + 532480, out + 4096);
}

// round 4
// speedup vs baseline: 1.4408x; 1.0478x over previous
#include <cuda_runtime.h>
#include <cstdint>
#include <math.h>

typedef unsigned long long ULL;

// ---------------- scratch offsets (floats) ----------------
#define OFF_WORDS 0ull                               // 4096*128
#define OFF_XG0F (OFF_WORDS + 524288ull)             // 4096*500
#define OFF_XG0B (OFF_XG0F + 2048000ull)
#define OFF_XG1F (OFF_XG0B + 2048000ull)
#define OFF_XG1B (OFF_XG1F + 2048000ull)
#define OFF_H0   (OFF_XG1B + 2048000ull)             // 4096*256
#define OFF_WE1  (OFF_H0   + 1048576ull)             // 4096*256
#define OFF_SCOR (OFF_WE1  + 1048576ull)             // 4096*400
#define OFF_WIH0 (OFF_SCOR + 1638400ull)             // 2*512*128
#define OFF_WIH1 (OFF_WIH0 + 131072ull)              // 2*512*256
#define OFF_SW   (OFF_WIH1 + 262144ull)              // 448*256
#define OFF_B0   (OFF_SW   + 114688ull)              // 2*512
#define OFF_B1   (OFF_B0   + 1024ull)                // 2*512
#define OFF_SB   (OFF_B1   + 1024ull)                // 448
#define SCR_TOT  (OFF_SB   + 448ull)

__device__ float g_scr[SCR_TOT];
__device__ int   g_tree[4096];
__device__ int   g_gidx[4096];

// ---------------- f32x2 helpers ----------------
__device__ __forceinline__ ULL pk2(float x, float y) {
    ULL r; asm("mov.b64 %0,{%1,%2};" : "=l"(r) : "f"(x), "f"(y)); return r;
}
__device__ __forceinline__ float2 upk2(ULL v) {
    float2 r; asm("mov.b64 {%0,%1},%2;" : "=f"(r.x), "=f"(r.y) : "l"(v)); return r;
}
__device__ __forceinline__ void fma2(ULL& c, ULL a, ULL b) {
    asm("fma.rn.f32x2 %0,%1,%2,%0;" : "+l"(c) : "l"(a), "l"(b));
}
__device__ __forceinline__ float sig_f(float x) {
    x = fminf(15.f, fmaxf(-15.f, x));
    float e; asm("ex2.approx.f32 %0,%1;" : "=f"(e) : "f"(-1.4426950408889634f * x));
    float r; asm("rcp.approx.f32 %0,%1;" : "=f"(r) : "f"(1.f + e));
    return r;
}
__device__ __forceinline__ float tanh_f(float x) {
    x = fminf(15.f, fmaxf(-15.f, x));
    float e; asm("ex2.approx.f32 %0,%1;" : "=f"(e) : "f"(2.885390081777927f * x));
    float r; asm("rcp.approx.f32 %0,%1;" : "=f"(r) : "f"(e + 1.f));
    return (e - 1.f) * r;
}
__device__ __forceinline__ uint32_t sa(const void* p) {
    return (uint32_t)__cvta_generic_to_shared(p);
}
__device__ __forceinline__ void cluster_sync_() {
    asm volatile("barrier.cluster.arrive.aligned;" ::: "memory");
    asm volatile("barrier.cluster.wait.aligned;" ::: "memory");
}

// ---------------- prep: pack/pad weights, biases, tree/gidx, zero pads ----------------
__global__ void k_prep(const int* __restrict__ tarc,
                       const float* __restrict__ l0fW, const float* __restrict__ l0bW,
                       const float* __restrict__ l1fW, const float* __restrict__ l1bW,
                       const float* __restrict__ ehW, const float* __restrict__ emW,
                       const float* __restrict__ lmW, const float* __restrict__ lhW,
                       const float* __restrict__ l0fb, const float* __restrict__ l0bb,
                       const float* __restrict__ l1fb, const float* __restrict__ l1bb,
                       const float* __restrict__ ehb, const float* __restrict__ emb,
                       const float* __restrict__ lmb, const float* __restrict__ lhb) {
    int idx = blockIdx.x * 256 + threadIdx.x;
    const int E0 = 131072, E1 = E0 + 262144, E2 = E1 + 114688, E3 = E2 + 1024,
              E4 = E3 + 1024, E5 = E4 + 448, E6 = E5 + 4096, E7 = E6 + 24576, E8 = E7 + 24576;
    if (idx < E0) {                       // WIH0 [2][512][128]
        int z = idx >> 16, r = idx & 65535, n = r >> 7, k = r & 127;
        const float* s = z ? l0bW : l0fW;
        g_scr[OFF_WIH0 + idx] = (n < 500 && k < 125) ? s[n * 125 + k] : 0.f;
    } else if (idx < E1) {                // WIH1 [2][512][256]
        int i = idx - E0, z = i >> 17, r = i & 131071, n = r >> 8, k = r & 255;
        const float* s = z ? l1bW : l1fW;
        g_scr[OFF_WIH1 + i] = (n < 500 && k < 250) ? s[n * 250 + k] : 0.f;
    } else if (idx < E2) {                // SW [448][256]: eh,em,lm,lh each 100 rows
        int i = idx - E1, n = i >> 8, k = i & 255;
        float v = 0.f;
        if (k < 250 && n < 400) {
            int sel = n / 100, nn = n - sel * 100;
            const float* s = sel == 0 ? ehW : sel == 1 ? emW : sel == 2 ? lmW : lhW;
            v = s[nn * 250 + k];
        }
        g_scr[OFF_SW + i] = v;
    } else if (idx < E3) {                // B0 [2][512]
        int i = idx - E2, z = i >> 9, n = i & 511;
        g_scr[OFF_B0 + i] = (n < 500) ? (z ? l0bb[n] : l0fb[n]) : 0.f;
    } else if (idx < E4) {                // B1 [2][512]
        int i = idx - E3, z = i >> 9, n = i & 511;
        g_scr[OFF_B1 + i] = (n < 500) ? (z ? l1bb[n] : l1fb[n]) : 0.f;
    } else if (idx < E5) {                // SB [448]
        int n = idx - E4;
        float v = 0.f;
        if (n < 400) {
            int sel = n / 100, nn = n - sel * 100;
            v = sel == 0 ? ehb[nn] : sel == 1 ? emb[nn] : sel == 2 ? lmb[nn] : lhb[nn];
        }
        g_scr[OFF_SB + n] = v;
    } else if (idx < E6) {                // tree + gidx
        int m = idx - E5;
        int v = ((m & 127) == 0) ? 0 : tarc[m];
        g_tree[m] = v;
        g_gidx[m] = (m >> 7) * 128 + v;
    } else if (idx < E7) {                // H0 pad cols 250..255
        int i = idx - E6, m = i / 6, c = i - m * 6;
        g_scr[OFF_H0 + (size_t)m * 256 + 250 + c] = 0.f;
    } else if (idx < E8) {                // WE1 pad cols
        int i = idx - E7, m = i / 6, c = i - m * 6;
        g_scr[OFF_WE1 + (size_t)m * 256 + 250 + c] = 0.f;
    }
}

// ---------------- embedding gather: words[4096,128] (padded) ----------------
__global__ void k_embed(const int* __restrict__ wid, const int* __restrict__ uid,
                        const float* __restrict__ wl, const float* __restrict__ tl) {
    int m = blockIdx.x, t = threadIdx.x;
    float* w = g_scr + OFF_WORDS + (size_t)m * 128;
    float v = 0.f;
    if (t < 100)      v = wl[(size_t)wid[m] * 100 + t];
    else if (t < 125) v = tl[(size_t)uid[m] * 25 + (t - 100)];
    w[t] = v;
}

// ---------------- GEMM: C[z][4096,N] = A[4096,K] @ Wp[z][Npad,K]^T + Bp[z] ----------------
__global__ void __launch_bounds__(256) k_gemm(const float* __restrict__ A,
                                              const float* __restrict__ Wp,
                                              const float* __restrict__ Bp,
                                              float* __restrict__ C,
                                              int N, int K, int ldWz, int bstride,
                                              long long zsC) {
    __shared__ __align__(16) float As[32][68];
    __shared__ __align__(16) float Ws[32][68];
    int z = blockIdx.z;
    const float* Wz = Wp + (size_t)z * ldWz;
    const float* bz = Bp + (size_t)z * bstride;
    float* Cz = C + (size_t)z * zsC;
    int t = threadIdx.x, tx = t & 15, ty = t >> 4;
    int m0 = blockIdx.y * 64, n0 = blockIdx.x * 64;
    int mf = t >> 3, kg = t & 7;

    ULL acc[2][4];
#pragma unroll
    for (int i = 0; i < 2; i++)
#pragma unroll
        for (int j = 0; j < 4; j++) acc[i][j] = 0ull;

    uint32_t aAddr = sa(&As[0][ty * 4]);

    for (int k0 = 0; k0 < K; k0 += 32) {
        float4 av1 = *(const float4*)(A  + (size_t)(m0 + mf) * K + k0 + kg * 4);
        float4 av2 = *(const float4*)(A  + (size_t)(m0 + mf + 32) * K + k0 + kg * 4);
        float4 wv1 = *(const float4*)(Wz + (size_t)(n0 + mf) * K + k0 + kg * 4);
        float4 wv2 = *(const float4*)(Wz + (size_t)(n0 + mf + 32) * K + k0 + kg * 4);
        As[kg * 4 + 0][mf] = av1.x; As[kg * 4 + 1][mf] = av1.y;
        As[kg * 4 + 2][mf] = av1.z; As[kg * 4 + 3][mf] = av1.w;
        As[kg * 4 + 0][mf + 32] = av2.x; As[kg * 4 + 1][mf + 32] = av2.y;
        As[kg * 4 + 2][mf + 32] = av2.z; As[kg * 4 + 3][mf + 32] = av2.w;
        Ws[kg * 4 + 0][mf] = wv1.x; Ws[kg * 4 + 1][mf] = wv1.y;
        Ws[kg * 4 + 2][mf] = wv1.z; Ws[kg * 4 + 3][mf] = wv1.w;
        Ws[kg * 4 + 0][mf + 32] = wv2.x; Ws[kg * 4 + 1][mf + 32] = wv2.y;
        Ws[kg * 4 + 2][mf + 32] = wv2.z; Ws[kg * 4 + 3][mf + 32] = wv2.w;
        __syncthreads();
#pragma unroll
        for (int k = 0; k < 32; k++) {
            ULL a01, a23;
            asm volatile("ld.shared.v2.u64 {%0,%1},[%2];"
                         : "=l"(a01), "=l"(a23) : "r"(aAddr + k * 272));
            float4 wv = *(const float4*)&Ws[k][tx * 4];
            ULL w0 = pk2(wv.x, wv.x), w1 = pk2(wv.y, wv.y);
            ULL w2 = pk2(wv.z, wv.z), w3 = pk2(wv.w, wv.w);
            fma2(acc[0][0], a01, w0); fma2(acc[1][0], a23, w0);
            fma2(acc[0][1], a01, w1); fma2(acc[1][1], a23, w1);
            fma2(acc[0][2], a01, w2); fma2(acc[1][2], a23, w2);
            fma2(acc[0][3], a01, w3); fma2(acc[1][3], a23, w3);
        }
        __syncthreads();
    }
    int n = n0 + tx * 4;
    float b0 = (n     < N) ? bz[n]     : 0.f;
    float b1 = (n + 1 < N) ? bz[n + 1] : 0.f;
    float b2 = (n + 2 < N) ? bz[n + 2] : 0.f;
    float b3 = (n + 3 < N) ? bz[n + 3] : 0.f;
#pragma unroll
    for (int i = 0; i < 2; i++) {
        float2 t0 = upk2(acc[i][0]), t1 = upk2(acc[i][1]);
        float2 t2 = upk2(acc[i][2]), t3 = upk2(acc[i][3]);
#pragma unroll
        for (int rr = 0; rr < 2; rr++) {
            int m = m0 + ty * 4 + i * 2 + rr;
            float4 v = rr ? make_float4(t0.y + b0, t1.y + b1, t2.y + b2, t3.y + b3)
                          : make_float4(t0.x + b0, t1.x + b1, t2.x + b2, t3.x + b3);
            if (n + 3 < N) {
                *(float4*)(Cz + (size_t)m * N + n) = v;
            } else {
                float vv[4] = {v.x, v.y, v.z, v.w};
                for (int jj = 0; jj < 4; jj++)
                    if (n + jj < N) Cz[(size_t)m * N + n + jj] = vv[jj];
            }
        }
    }
}

// ---------------- LSTM scan: 64 (b,dir) x 2-CTA clusters ----------------
// Local/remote gemv split: local partial for step s+1 computed immediately
// after h(s), overlapping the DSMEM exchange. One mbarrier per CTA; peer-only
// per-thread release-arrives (count = peer cell count).
__global__ void __cluster_dims__(2, 1, 1) __launch_bounds__(256, 1)
k_scan(const float* __restrict__ xgf, const float* __restrict__ xgb,
       const float* __restrict__ whf, const float* __restrict__ whb,
       float* __restrict__ hout) {
    __shared__ __align__(16) float hloc[2][64];
    __shared__ __align__(16) float hrem[2][64];
    __shared__ float sact[256];
    __shared__ __align__(8) unsigned long long mbar;
    int cta = blockIdx.x;
    uint32_t rk = cta & 1;
    int p = cta >> 1, b = p & 31, dir = p >> 5;
    const float* xg  = dir ? xgb : xgf;
    const float* Whh = dir ? whb : whf;
    int jbase = rk ? 63 : 0, cnt = rk ? 62 : 63;
    int pbase = rk ? 0 : 63,  pcnt = rk ? 63 : 62;
    int t = threadIdx.x, q = t >> 6, jj = t & 63;
    bool act = jj < cnt;
    int grow = q * 125 + jbase + (act ? jj : 0);
    const float* wrow = Whh + (size_t)grow * 125;

    ULL wl[32], wr[32];
#pragma unroll
    for (int kk = 0; kk < 32; kk++) {
        float f0 = (act && 2 * kk     < cnt) ? wrow[jbase + 2 * kk]     : 0.f;
        float f1 = (act && 2 * kk + 1 < cnt) ? wrow[jbase + 2 * kk + 1] : 0.f;
        wl[kk] = pk2(f0, f1);
        f0 = (act && 2 * kk     < pcnt) ? wrow[pbase + 2 * kk]     : 0.f;
        f1 = (act && 2 * kk + 1 < pcnt) ? wrow[pbase + 2 * kk + 1] : 0.f;
        wr[kk] = pk2(f0, f1);
    }
    if (t < 64) { hloc[0][t] = 0.f; hloc[1][t] = 0.f; hrem[0][t] = 0.f; hrem[1][t] = 0.f; }
    uint32_t mb = sa(&mbar);
    if (t == 0)
        asm volatile("mbarrier.init.shared.b64 [%0], %1;" :: "r"(mb), "r"((uint32_t)pcnt) : "memory");
    cluster_sync_();

    uint32_t hremA = sa(&hrem[0][0]);
    uint32_t hlocA = sa(&hloc[0][0]);
    uint32_t rhrem, rmb;
    asm("mapa.shared::cluster.u32 %0,%1,%2;" : "=r"(rhrem) : "r"(hremA), "r"(rk ^ 1u));
    asm("mapa.shared::cluster.u32 %0,%1,%2;" : "=r"(rmb)   : "r"(mb),    "r"(rk ^ 1u));

    float c = 0.f, pl = 0.f;
    uint32_t ph = 0;
    const size_t brow = (size_t)b * 128;
    int tt0 = dir ? 127 : 0;
    float xv = act ? xg[(brow + tt0) * 500 + grow] : 0.f;

    for (int s = 0; s < 128; s++) {
        int tt = dir ? (127 - s) : s;
        if (s > 0) {
            uint32_t done;
            do {
                asm volatile("{\n\t.reg .pred P;\n\t"
                             "mbarrier.try_wait.parity.acquire.cluster.shared::cta.b64 P,[%1],%2,0x989680;\n\t"
                             "selp.b32 %0,1,0,P;\n\t}"
                             : "=r"(done) : "r"(mb), "r"(ph) : "memory");
            } while (!done);
            ph ^= 1;
        }
        // remote gemv over hrem[(s-1)&1] (zeros for s=0)
        uint32_t rb = hremA + (((s + 1) & 1) << 8);
        ULL a0 = 0ull, a1 = 0ull, a2 = 0ull, a3 = 0ull;
#pragma unroll
        for (int i = 0; i < 16; i++) {
            ULL h01, h23;
            asm volatile("ld.shared.v2.u64 {%0,%1},[%2];"
                         : "=l"(h01), "=l"(h23) : "r"(rb + i * 16));
            if (i & 1) { fma2(a2, h01, wr[2 * i]); fma2(a3, h23, wr[2 * i + 1]); }
            else       { fma2(a0, h01, wr[2 * i]); fma2(a1, h23, wr[2 * i + 1]); }
        }
        float2 f0 = upk2(a0), f1 = upk2(a1), f2 = upk2(a2), f3 = upk2(a3);
        float g = ((f0.x + f0.y) + (f1.x + f1.y)) + ((f2.x + f2.y) + (f3.x + f3.y)) + pl + xv;
        if (s + 1 < 128) {
            int tn = dir ? (126 - s) : (s + 1);
            xv = act ? xg[(brow + tn) * 500 + grow] : 0.f;
        }
        sact[t] = (q == 2) ? tanh_f(g) : sig_f(g);
        __syncthreads();
        if (q == 0 && act) {
            float si = sact[jj], sf = sact[64 + jj], tg = sact[128 + jj], so = sact[192 + jj];
            c = sf * c + si * tg;
            float h = so * tanh_f(c);
            int lbuf = s & 1;
            hloc[lbuf][jj] = h;
            asm volatile("st.shared::cluster.f32 [%0],%1;"
                         :: "r"(rhrem + (uint32_t)((lbuf << 8) + (jj << 2))), "f"(h) : "memory");
            hout[(brow + tt) * 256 + dir * 125 + jbase + jj] = h;
            asm volatile("mbarrier.arrive.release.cluster.shared::cluster.b64 _,[%0];"
                         :: "r"(rmb) : "memory");
        }
        __syncthreads();
        // local gemv over hloc[s&1] -> partial for step s+1
        uint32_t lb = hlocA + ((s & 1) << 8);
        a0 = 0ull; a1 = 0ull; a2 = 0ull; a3 = 0ull;
#pragma unroll
        for (int i = 0; i < 16; i++) {
            ULL h01, h23;
            asm volatile("ld.shared.v2.u64 {%0,%1},[%2];"
                         : "=l"(h01), "=l"(h23) : "r"(lb + i * 16));
            if (i & 1) { fma2(a2, h01, wl[2 * i]); fma2(a3, h23, wl[2 * i + 1]); }
            else       { fma2(a0, h01, wl[2 * i]); fma2(a1, h23, wl[2 * i + 1]); }
        }
        f0 = upk2(a0); f1 = upk2(a1); f2 = upk2(a2); f3 = upk2(a3);
        pl = ((f0.x + f0.y) + (f1.x + f1.y)) + ((f2.x + f2.y) + (f3.x + f3.y));
    }
    cluster_sync_();
}

// ---------------- biaffine arc scores + margin + argmax ----------------
__global__ void __launch_bounds__(256) k_arc(const float* __restrict__ esW,
                                             const float* __restrict__ esb,
                                             float* __restrict__ arc_out,
                                             float* __restrict__ parsed_out) {
    extern __shared__ float sm[];
    float* wms   = sm;                 // 128*101
    float* whs   = sm + 128 * 101;     // 16*101
    float* esw   = whs + 16 * 101;     // 100
    float* baseS = esw + 100;          // 1
    int*   treei = (int*)(baseS + 1);  // 16
    const float S = 2.885390081777927f; // 2*log2(e)
    int b = blockIdx.y, i0 = blockIdx.x * 16;
    int t = threadIdx.x;
    const float* wm = g_scr + OFF_SCOR + (size_t)b * 128 * 400 + 100;
    const float* wh = g_scr + OFF_SCOR + ((size_t)b * 128 + i0) * 400;
    for (int idx = t; idx < 12800; idx += 256) {
        int j = idx / 100, h = idx - j * 100;
        wms[j * 101 + h] = wm[(size_t)j * 400 + h] * S;
    }
    for (int idx = t; idx < 1600; idx += 256) {
        int ii = idx / 100, h = idx - ii * 100;
        whs[ii * 101 + h] = wh[(size_t)ii * 400 + h] * S;
    }
    if (t < 100) esw[t] = -2.f * esW[t];
    if (t == 0) {
        float ssum = 0.f;
        for (int h = 0; h < 100; h++) ssum += esW[h];
        baseS[0] = ssum + esb[0] + 1.f;
    }
    if (t < 16) treei[t] = g_tree[b * 128 + i0 + t];
    __syncthreads();

    int ii = t >> 4, jl = t & 15;
    int i = i0 + ii;
    int tgt = treei[ii];
    float base = baseS[0];
    float best = -1e30f; int bj = 0;
    float* arow = arc_out + ((size_t)b * 128 + i) * 128;
    const float* Arow = whs + ii * 101;
    for (int jt = 0; jt < 8; jt++) {
        int j = jl + 16 * jt;
        const float* Brow = wms + j * 101;
        float acc = 0.f;
#pragma unroll
        for (int h = 0; h < 100; h++) {
            float x = Arow[h] + Brow[h];
            float e; asm("ex2.approx.f32 %0, %1;" : "=f"(e) : "f"(x));
            float rr; asm("rcp.approx.f32 %0, %1;" : "=f"(rr) : "f"(1.f + e));
            acc = fmaf(esw[h], rr, acc);
        }
        float sc = base + acc - ((j == tgt) ? 1.f : 0.f);
        arow[j] = sc;
        if (sc > best) { best = sc; bj = j; }
    }
    for (int off = 8; off; off >>= 1) {
        float ob = __shfl_xor_sync(0xffffffffu, best, off);
        int   oj = __shfl_xor_sync(0xffffffffu, bj, off);
        if (ob > best || (ob == best && oj < bj)) { best = ob; bj = oj; }
    }
    if (jl == 0) parsed_out[b * 128 + i] = (float)bj;
}

// ---------------- rel scores + argmax (head gather post-projection) ----------------
__global__ void k_rel(const float* __restrict__ lsW, const float* __restrict__ lsb,
                      float* __restrict__ rel_out, float* __restrict__ pred_out) {
    __shared__ float th[100];
    __shared__ float sc[50];
    int m = blockIdx.x, t = threadIdx.x;
    const float* rm = g_scr + OFF_SCOR + (size_t)m * 400 + 200;
    const float* rh = g_scr + OFF_SCOR + (size_t)g_gidx[m] * 400 + 300;
    for (int h = t; h < 100; h += 64) th[h] = tanhf(rm[h] + rh[h]);
    __syncthreads();
    if (t < 50) {
        float acc = lsb[t];
        const float* wr = lsW + t * 100;
#pragma unroll 10
        for (int h = 0; h < 100; h++) acc = fmaf(th[h], wr[h], acc);
        rel_out[(size_t)m * 50 + t] = acc;
        sc[t] = acc;
    }
    __syncthreads();
    if (t == 0) {
        float best = sc[0]; int bl = 0;
        for (int l = 1; l < 50; l++) if (sc[l] > best) { best = sc[l]; bl = l; }
        pred_out[m] = (float)bl;
    }
}

// ---------------- launch ----------------
extern "C" void kernel_launch(void* const* d_in, const int* in_sizes, int n_in,
                              void* d_out, int out_size) {
    const int* wid  = (const int*)d_in[0];
    const int* uid  = (const int*)d_in[1];
    const int* tarc = (const int*)d_in[2];
    const float* wl = (const float*)d_in[3];
    const float* tl = (const float*)d_in[4];
    const float* l0f_Wih = (const float*)d_in[5];
    const float* l0f_Whh = (const float*)d_in[6];
    const float* l0f_b   = (const float*)d_in[7];
    const float* l0b_Wih = (const float*)d_in[8];
    const float* l0b_Whh = (const float*)d_in[9];
    const float* l0b_b   = (const float*)d_in[10];
    const float* l1f_Wih = (const float*)d_in[11];
    const float* l1f_Whh = (const float*)d_in[12];
    const float* l1f_b   = (const float*)d_in[13];
    const float* l1b_Wih = (const float*)d_in[14];
    const float* l1b_Whh = (const float*)d_in[15];
    const float* l1b_b   = (const float*)d_in[16];
    const float* ehW = (const float*)d_in[17];
    const float* ehb = (const float*)d_in[18];
    const float* emW = (const float*)d_in[19];
    const float* emb = (const float*)d_in[20];
    const float* esW = (const float*)d_in[21];
    const float* esb = (const float*)d_in[22];
    const float* lhW = (const float*)d_in[23];
    const float* lhb = (const float*)d_in[24];
    const float* lmW = (const float*)d_in[25];
    const float* lmb = (const float*)d_in[26];
    const float* lsW = (const float*)d_in[27];
    const float* lsb = (const float*)d_in[28];
    float* out = (float*)d_out;

    float* scr = nullptr;
    cudaGetSymbolAddress((void**)&scr, g_scr);
    float* WORDS = scr + OFF_WORDS;
    float* XG0F = scr + OFF_XG0F;
    float* XG0B = scr + OFF_XG0B;
    float* XG1F = scr + OFF_XG1F;
    float* XG1B = scr + OFF_XG1B;
    float* H0   = scr + OFF_H0;
    float* WE1  = scr + OFF_WE1;
    float* SCOR = scr + OFF_SCOR;
    float* WIH0 = scr + OFF_WIH0;
    float* WIH1 = scr + OFF_WIH1;
    float* SW   = scr + OFF_SW;
    float* B0   = scr + OFF_B0;
    float* B1   = scr + OFF_B1;
    float* SB   = scr + OFF_SB;

    k_prep<<<2202, 256>>>(tarc, l0f_Wih, l0b_Wih, l1f_Wih, l1b_Wih,
                          ehW, emW, lmW, lhW,
                          l0f_b, l0b_b, l1f_b, l1b_b, ehb, emb, lmb, lhb);
    k_embed<<<4096, 128>>>(wid, uid, wl, tl);

    k_gemm<<<dim3(8, 64, 2), 256>>>(WORDS, WIH0, B0, XG0F, 500, 128,
                                    512 * 128, 512, 2048000LL);
    k_scan<<<128, 256>>>(XG0F, XG0B, l0f_Whh, l0b_Whh, H0);
    k_gemm<<<dim3(8, 64, 2), 256>>>(H0, WIH1, B1, XG1F, 500, 256,
                                    512 * 256, 512, 2048000LL);
    k_scan<<<128, 256>>>(XG1F, XG1B, l1f_Whh, l1b_Whh, WE1);
    k_gemm<<<dim3(7, 64, 1), 256>>>(WE1, SW, SB, SCOR, 400, 256, 0, 0, 0LL);

    cudaFuncSetAttribute(k_arc, cudaFuncAttributeMaxDynamicSharedMemorySize, 60000);
    k_arc<<<dim3(8, 32), 256, 58656>>>(esW, esb, out + 8192, out);
    k_rel<<<4096, 64>>>(lsW, lsb, out + 532480, out + 4096);
}

// round 5
// speedup vs baseline: 1.5553x; 1.0794x over previous
#include <cuda_runtime.h>
#include <cstdint>
#include <math.h>

typedef unsigned long long ULL;

// ---------------- scratch offsets (floats) ----------------
#define OFF_WORDS 0ull                               // 4096*128
#define OFF_XG0F (OFF_WORDS + 524288ull)             // 4096*500
#define OFF_XG0B (OFF_XG0F + 2048000ull)
#define OFF_XG1F (OFF_XG0B + 2048000ull)
#define OFF_XG1B (OFF_XG1F + 2048000ull)
#define OFF_H0   (OFF_XG1B + 2048000ull)             // 4096*256
#define OFF_WE1  (OFF_H0   + 1048576ull)             // 4096*256
#define OFF_SCOR (OFF_WE1  + 1048576ull)             // 4096*400
#define OFF_WIH0 (OFF_SCOR + 1638400ull)             // 2*512*128
#define OFF_WIH1 (OFF_WIH0 + 131072ull)              // 2*512*256
#define OFF_SW   (OFF_WIH1 + 262144ull)              // 448*256
#define OFF_B0   (OFF_SW   + 114688ull)              // 2*512
#define OFF_B1   (OFF_B0   + 1024ull)                // 2*512
#define OFF_SB   (OFF_B1   + 1024ull)                // 448
#define SCR_TOT  (OFF_SB   + 448ull)

__device__ float g_scr[SCR_TOT];
__device__ int   g_tree[4096];
__device__ int   g_gidx[4096];

// ---------------- f32x2 helpers ----------------
__device__ __forceinline__ ULL pk2(float x, float y) {
    ULL r; asm("mov.b64 %0,{%1,%2};" : "=l"(r) : "f"(x), "f"(y)); return r;
}
__device__ __forceinline__ float2 upk2(ULL v) {
    float2 r; asm("mov.b64 {%0,%1},%2;" : "=f"(r.x), "=f"(r.y) : "l"(v)); return r;
}
__device__ __forceinline__ void fma2(ULL& c, ULL a, ULL b) {
    asm("fma.rn.f32x2 %0,%1,%2,%0;" : "+l"(c) : "l"(a), "l"(b));
}
__device__ __forceinline__ float sig_f(float x) {
    x = fminf(15.f, fmaxf(-15.f, x));
    float e; asm("ex2.approx.f32 %0,%1;" : "=f"(e) : "f"(-1.4426950408889634f * x));
    float r; asm("rcp.approx.f32 %0,%1;" : "=f"(r) : "f"(1.f + e));
    return r;
}
__device__ __forceinline__ float tanh_f(float x) {
    x = fminf(15.f, fmaxf(-15.f, x));
    float e; asm("ex2.approx.f32 %0,%1;" : "=f"(e) : "f"(2.885390081777927f * x));
    float r; asm("rcp.approx.f32 %0,%1;" : "=f"(r) : "f"(e + 1.f));
    return (e - 1.f) * r;
}
__device__ __forceinline__ uint32_t sa(const void* p) {
    return (uint32_t)__cvta_generic_to_shared(p);
}
__device__ __forceinline__ void cluster_sync_() {
    asm volatile("barrier.cluster.arrive.aligned;" ::: "memory");
    asm volatile("barrier.cluster.wait.aligned;" ::: "memory");
}

// ---------------- prep: pack/pad weights, biases, tree/gidx, zero pads ----------------
__global__ void k_prep(const int* __restrict__ tarc,
                       const float* __restrict__ l0fW, const float* __restrict__ l0bW,
                       const float* __restrict__ l1fW, const float* __restrict__ l1bW,
                       const float* __restrict__ ehW, const float* __restrict__ emW,
                       const float* __restrict__ lmW, const float* __restrict__ lhW,
                       const float* __restrict__ l0fb, const float* __restrict__ l0bb,
                       const float* __restrict__ l1fb, const float* __restrict__ l1bb,
                       const float* __restrict__ ehb, const float* __restrict__ emb,
                       const float* __restrict__ lmb, const float* __restrict__ lhb) {
    int idx = blockIdx.x * 256 + threadIdx.x;
    const int E0 = 131072, E1 = E0 + 262144, E2 = E1 + 114688, E3 = E2 + 1024,
              E4 = E3 + 1024, E5 = E4 + 448, E6 = E5 + 4096, E7 = E6 + 24576, E8 = E7 + 24576;
    if (idx < E0) {                       // WIH0 [2][512][128]
        int z = idx >> 16, r = idx & 65535, n = r >> 7, k = r & 127;
        const float* s = z ? l0bW : l0fW;
        g_scr[OFF_WIH0 + idx] = (n < 500 && k < 125) ? s[n * 125 + k] : 0.f;
    } else if (idx < E1) {                // WIH1 [2][512][256]
        int i = idx - E0, z = i >> 17, r = i & 131071, n = r >> 8, k = r & 255;
        const float* s = z ? l1bW : l1fW;
        g_scr[OFF_WIH1 + i] = (n < 500 && k < 250) ? s[n * 250 + k] : 0.f;
    } else if (idx < E2) {                // SW [448][256]: eh,em,lm,lh each 100 rows
        int i = idx - E1, n = i >> 8, k = i & 255;
        float v = 0.f;
        if (k < 250 && n < 400) {
            int sel = n / 100, nn = n - sel * 100;
            const float* s = sel == 0 ? ehW : sel == 1 ? emW : sel == 2 ? lmW : lhW;
            v = s[nn * 250 + k];
        }
        g_scr[OFF_SW + i] = v;
    } else if (idx < E3) {                // B0 [2][512]
        int i = idx - E2, z = i >> 9, n = i & 511;
        g_scr[OFF_B0 + i] = (n < 500) ? (z ? l0bb[n] : l0fb[n]) : 0.f;
    } else if (idx < E4) {                // B1 [2][512]
        int i = idx - E3, z = i >> 9, n = i & 511;
        g_scr[OFF_B1 + i] = (n < 500) ? (z ? l1bb[n] : l1fb[n]) : 0.f;
    } else if (idx < E5) {                // SB [448]
        int n = idx - E4;
        float v = 0.f;
        if (n < 400) {
            int sel = n / 100, nn = n - sel * 100;
            v = sel == 0 ? ehb[nn] : sel == 1 ? emb[nn] : sel == 2 ? lmb[nn] : lhb[nn];
        }
        g_scr[OFF_SB + n] = v;
    } else if (idx < E6) {                // tree + gidx
        int m = idx - E5;
        int v = ((m & 127) == 0) ? 0 : tarc[m];
        g_tree[m] = v;
        g_gidx[m] = (m >> 7) * 128 + v;
    } else if (idx < E7) {                // H0 pad cols 250..255
        int i = idx - E6, m = i / 6, c = i - m * 6;
        g_scr[OFF_H0 + (size_t)m * 256 + 250 + c] = 0.f;
    } else if (idx < E8) {                // WE1 pad cols
        int i = idx - E7, m = i / 6, c = i - m * 6;
        g_scr[OFF_WE1 + (size_t)m * 256 + 250 + c] = 0.f;
    }
}

// ---------------- embedding gather: words[4096,128] (padded) ----------------
__global__ void k_embed(const int* __restrict__ wid, const int* __restrict__ uid,
                        const float* __restrict__ wl, const float* __restrict__ tl) {
    int m = blockIdx.x, t = threadIdx.x;
    float* w = g_scr + OFF_WORDS + (size_t)m * 128;
    float v = 0.f;
    if (t < 100)      v = wl[(size_t)wid[m] * 100 + t];
    else if (t < 125) v = tl[(size_t)uid[m] * 25 + (t - 100)];
    w[t] = v;
}

// ---------------- GEMM: C[z][4096,N] = A[4096,K] @ Wp[z][Npad,K]^T + Bp[z] ----------------
__global__ void __launch_bounds__(256) k_gemm(const float* __restrict__ A,
                                              const float* __restrict__ Wp,
                                              const float* __restrict__ Bp,
                                              float* __restrict__ C,
                                              int N, int K, int ldWz, int bstride,
                                              long long zsC) {
    __shared__ __align__(16) float As[32][68];
    __shared__ __align__(16) float Ws[32][68];
    int z = blockIdx.z;
    const float* Wz = Wp + (size_t)z * ldWz;
    const float* bz = Bp + (size_t)z * bstride;
    float* Cz = C + (size_t)z * zsC;
    int t = threadIdx.x, tx = t & 15, ty = t >> 4;
    int m0 = blockIdx.y * 64, n0 = blockIdx.x * 64;
    int mf = t >> 3, kg = t & 7;

    ULL acc[2][4];
#pragma unroll
    for (int i = 0; i < 2; i++)
#pragma unroll
        for (int j = 0; j < 4; j++) acc[i][j] = 0ull;

    uint32_t aAddr = sa(&As[0][ty * 4]);

    for (int k0 = 0; k0 < K; k0 += 32) {
        float4 av1 = *(const float4*)(A  + (size_t)(m0 + mf) * K + k0 + kg * 4);
        float4 av2 = *(const float4*)(A  + (size_t)(m0 + mf + 32) * K + k0 + kg * 4);
        float4 wv1 = *(const float4*)(Wz + (size_t)(n0 + mf) * K + k0 + kg * 4);
        float4 wv2 = *(const float4*)(Wz + (size_t)(n0 + mf + 32) * K + k0 + kg * 4);
        As[kg * 4 + 0][mf] = av1.x; As[kg * 4 + 1][mf] = av1.y;
        As[kg * 4 + 2][mf] = av1.z; As[kg * 4 + 3][mf] = av1.w;
        As[kg * 4 + 0][mf + 32] = av2.x; As[kg * 4 + 1][mf + 32] = av2.y;
        As[kg * 4 + 2][mf + 32] = av2.z; As[kg * 4 + 3][mf + 32] = av2.w;
        Ws[kg * 4 + 0][mf] = wv1.x; Ws[kg * 4 + 1][mf] = wv1.y;
        Ws[kg * 4 + 2][mf] = wv1.z; Ws[kg * 4 + 3][mf] = wv1.w;
        Ws[kg * 4 + 0][mf + 32] = wv2.x; Ws[kg * 4 + 1][mf + 32] = wv2.y;
        Ws[kg * 4 + 2][mf + 32] = wv2.z; Ws[kg * 4 + 3][mf + 32] = wv2.w;
        __syncthreads();
#pragma unroll
        for (int k = 0; k < 32; k++) {
            ULL a01, a23;
            asm volatile("ld.shared.v2.u64 {%0,%1},[%2];"
                         : "=l"(a01), "=l"(a23) : "r"(aAddr + k * 272));
            float4 wv = *(const float4*)&Ws[k][tx * 4];
            ULL w0 = pk2(wv.x, wv.x), w1 = pk2(wv.y, wv.y);
            ULL w2 = pk2(wv.z, wv.z), w3 = pk2(wv.w, wv.w);
            fma2(acc[0][0], a01, w0); fma2(acc[1][0], a23, w0);
            fma2(acc[0][1], a01, w1); fma2(acc[1][1], a23, w1);
            fma2(acc[0][2], a01, w2); fma2(acc[1][2], a23, w2);
            fma2(acc[0][3], a01, w3); fma2(acc[1][3], a23, w3);
        }
        __syncthreads();
    }
    int n = n0 + tx * 4;
    float b0 = (n     < N) ? bz[n]     : 0.f;
    float b1 = (n + 1 < N) ? bz[n + 1] : 0.f;
    float b2 = (n + 2 < N) ? bz[n + 2] : 0.f;
    float b3 = (n + 3 < N) ? bz[n + 3] : 0.f;
#pragma unroll
    for (int i = 0; i < 2; i++) {
        float2 t0 = upk2(acc[i][0]), t1 = upk2(acc[i][1]);
        float2 t2 = upk2(acc[i][2]), t3 = upk2(acc[i][3]);
#pragma unroll
        for (int rr = 0; rr < 2; rr++) {
            int m = m0 + ty * 4 + i * 2 + rr;
            float4 v = rr ? make_float4(t0.y + b0, t1.y + b1, t2.y + b2, t3.y + b3)
                          : make_float4(t0.x + b0, t1.x + b1, t2.x + b2, t3.x + b3);
            if (n + 3 < N) {
                *(float4*)(Cz + (size_t)m * N + n) = v;
            } else {
                float vv[4] = {v.x, v.y, v.z, v.w};
                for (int jj = 0; jj < 4; jj++)
                    if (n + jj < N) Cz[(size_t)m * N + n + jj] = vv[jj];
            }
        }
    }
}

// ---------------- LSTM scan: 64 (b,dir) x 2-CTA clusters ----------------
// Fabric-transaction-minimized exchange: h lands in local smem; 16 threads
// forward it to the peer as float4 vector stores + their own release-arrive
// (mbarrier count=16). Local gemv for s+1 overlaps the fabric latency.
__global__ void __cluster_dims__(2, 1, 1) __launch_bounds__(256, 1)
k_scan(const float* __restrict__ xgf, const float* __restrict__ xgb,
       const float* __restrict__ whf, const float* __restrict__ whb,
       float* __restrict__ hout) {
    __shared__ __align__(16) float hloc[2][64];
    __shared__ __align__(16) float hrem[2][64];
    __shared__ float sact[256];
    __shared__ __align__(8) unsigned long long mbar;
    int cta = blockIdx.x;
    uint32_t rk = cta & 1;
    int p = cta >> 1, b = p & 31, dir = p >> 5;
    const float* xg  = dir ? xgb : xgf;
    const float* Whh = dir ? whb : whf;
    int jbase = rk ? 63 : 0, cnt = rk ? 62 : 63;
    int pbase = rk ? 0 : 63,  pcnt = rk ? 63 : 62;
    int t = threadIdx.x, q = t >> 6, jj = t & 63;
    bool act = jj < cnt;
    int grow = q * 125 + jbase + (act ? jj : 0);
    const float* wrow = Whh + (size_t)grow * 125;

    ULL wl[32], wr[32];
#pragma unroll
    for (int kk = 0; kk < 32; kk++) {
        float f0 = (act && 2 * kk     < cnt) ? wrow[jbase + 2 * kk]     : 0.f;
        float f1 = (act && 2 * kk + 1 < cnt) ? wrow[jbase + 2 * kk + 1] : 0.f;
        wl[kk] = pk2(f0, f1);
        f0 = (act && 2 * kk     < pcnt) ? wrow[pbase + 2 * kk]     : 0.f;
        f1 = (act && 2 * kk + 1 < pcnt) ? wrow[pbase + 2 * kk + 1] : 0.f;
        wr[kk] = pk2(f0, f1);
    }
    if (t < 64) { hloc[0][t] = 0.f; hloc[1][t] = 0.f; hrem[0][t] = 0.f; hrem[1][t] = 0.f; }
    uint32_t mb = sa(&mbar);
    if (t == 0)
        asm volatile("mbarrier.init.shared.b64 [%0], %1;" :: "r"(mb), "r"(16u) : "memory");
    cluster_sync_();

    uint32_t hremA = sa(&hrem[0][0]);
    uint32_t hlocA = sa(&hloc[0][0]);
    uint32_t rhrem, rmb;
    asm("mapa.shared::cluster.u32 %0,%1,%2;" : "=r"(rhrem) : "r"(hremA), "r"(rk ^ 1u));
    asm("mapa.shared::cluster.u32 %0,%1,%2;" : "=r"(rmb)   : "r"(mb),    "r"(rk ^ 1u));

    float c = 0.f, pl = 0.f;
    uint32_t ph = 0;
    const size_t brow = (size_t)b * 128;
    int tt0 = dir ? 127 : 0;
    float xv = act ? xg[(brow + tt0) * 500 + grow] : 0.f;

    for (int s = 0; s < 128; s++) {
        int tt = dir ? (127 - s) : s;
        if (s > 0) {
            uint32_t done;
            do {
                asm volatile("{\n\t.reg .pred P;\n\t"
                             "mbarrier.try_wait.parity.acquire.cluster.shared::cta.b64 P,[%1],%2,0x989680;\n\t"
                             "selp.b32 %0,1,0,P;\n\t}"
                             : "=r"(done) : "r"(mb), "r"(ph) : "memory");
            } while (!done);
            ph ^= 1;
        }
        // remote gemv over hrem[(s-1)&1] (zeros for s=0)
        uint32_t rb = hremA + (((s + 1) & 1) << 8);
        ULL a0 = 0ull, a1 = 0ull, a2 = 0ull, a3 = 0ull;
#pragma unroll
        for (int i = 0; i < 16; i++) {
            ULL h01, h23;
            asm volatile("ld.shared.v2.u64 {%0,%1},[%2];"
                         : "=l"(h01), "=l"(h23) : "r"(rb + i * 16));
            if (i & 1) { fma2(a2, h01, wr[2 * i]); fma2(a3, h23, wr[2 * i + 1]); }
            else       { fma2(a0, h01, wr[2 * i]); fma2(a1, h23, wr[2 * i + 1]); }
        }
        float2 f0 = upk2(a0), f1 = upk2(a1), f2 = upk2(a2), f3 = upk2(a3);
        float g = ((f0.x + f0.y) + (f1.x + f1.y)) + ((f2.x + f2.y) + (f3.x + f3.y)) + pl + xv;
        if (s + 1 < 128) {
            int tn = dir ? (126 - s) : (s + 1);
            xv = act ? xg[(brow + tn) * 500 + grow] : 0.f;
        }
        sact[t] = (q == 2) ? tanh_f(g) : sig_f(g);
        __syncthreads();
        int lbuf = s & 1;
        if (q == 0 && act) {
            float si = sact[jj], sf = sact[64 + jj], tg = sact[128 + jj], so = sact[192 + jj];
            c = sf * c + si * tg;
            float h = so * tanh_f(c);
            hloc[lbuf][jj] = h;
            hout[(brow + tt) * 256 + dir * 125 + jbase + jj] = h;
        }
        __syncthreads();
        if (t < 16) {
            // forward 4 h values to the peer as one 16B packet + own release-arrive
            const float4 hv = *(const float4*)&hloc[lbuf][t * 4];
            asm volatile("st.shared::cluster.v4.b32 [%0],{%1,%2,%3,%4};"
                         :: "r"(rhrem + (uint32_t)((lbuf << 8) + (t << 4))),
                            "r"(__float_as_uint(hv.x)), "r"(__float_as_uint(hv.y)),
                            "r"(__float_as_uint(hv.z)), "r"(__float_as_uint(hv.w))
                         : "memory");
            asm volatile("mbarrier.arrive.release.cluster.shared::cluster.b64 _,[%0];"
                         :: "r"(rmb) : "memory");
        }
        // local gemv over hloc[s&1] -> partial for step s+1 (overlaps fabric)
        uint32_t lb = hlocA + (lbuf << 8);
        a0 = 0ull; a1 = 0ull; a2 = 0ull; a3 = 0ull;
#pragma unroll
        for (int i = 0; i < 16; i++) {
            ULL h01, h23;
            asm volatile("ld.shared.v2.u64 {%0,%1},[%2];"
                         : "=l"(h01), "=l"(h23) : "r"(lb + i * 16));
            if (i & 1) { fma2(a2, h01, wl[2 * i]); fma2(a3, h23, wl[2 * i + 1]); }
            else       { fma2(a0, h01, wl[2 * i]); fma2(a1, h23, wl[2 * i + 1]); }
        }
        f0 = upk2(a0); f1 = upk2(a1); f2 = upk2(a2); f3 = upk2(a3);
        pl = ((f0.x + f0.y) + (f1.x + f1.y)) + ((f2.x + f2.y) + (f3.x + f3.y));
    }
    cluster_sync_();
}

// ---------------- biaffine arc scores + margin + argmax ----------------
__global__ void __launch_bounds__(256) k_arc(const float* __restrict__ esW,
                                             const float* __restrict__ esb,
                                             float* __restrict__ arc_out,
                                             float* __restrict__ parsed_out) {
    extern __shared__ float sm[];
    float* wms   = sm;                 // 128*101
    float* whs   = sm + 128 * 101;     // 16*101
    float* esw   = whs + 16 * 101;     // 100
    float* baseS = esw + 100;          // 1
    int*   treei = (int*)(baseS + 1);  // 16
    const float S = 2.885390081777927f; // 2*log2(e)
    int b = blockIdx.y, i0 = blockIdx.x * 16;
    int t = threadIdx.x;
    const float* wm = g_scr + OFF_SCOR + (size_t)b * 128 * 400 + 100;
    const float* wh = g_scr + OFF_SCOR + ((size_t)b * 128 + i0) * 400;
    for (int idx = t; idx < 12800; idx += 256) {
        int j = idx / 100, h = idx - j * 100;
        wms[j * 101 + h] = wm[(size_t)j * 400 + h] * S;
    }
    for (int idx = t; idx < 1600; idx += 256) {
        int ii = idx / 100, h = idx - ii * 100;
        whs[ii * 101 + h] = wh[(size_t)ii * 400 + h] * S;
    }
    if (t < 100) esw[t] = -2.f * esW[t];
    if (t == 0) {
        float ssum = 0.f;
        for (int h = 0; h < 100; h++) ssum += esW[h];
        baseS[0] = ssum + esb[0] + 1.f;
    }
    if (t < 16) treei[t] = g_tree[b * 128 + i0 + t];
    __syncthreads();

    int ii = t >> 4, jl = t & 15;
    int i = i0 + ii;
    int tgt = treei[ii];
    float base = baseS[0];
    float best = -1e30f; int bj = 0;
    float* arow = arc_out + ((size_t)b * 128 + i) * 128;
    const float* Arow = whs + ii * 101;
    for (int jt = 0; jt < 8; jt++) {
        int j = jl + 16 * jt;
        const float* Brow = wms + j * 101;
        float acc = 0.f;
#pragma unroll
        for (int h = 0; h < 100; h++) {
            float x = Arow[h] + Brow[h];
            float e; asm("ex2.approx.f32 %0, %1;" : "=f"(e) : "f"(x));
            float rr; asm("rcp.approx.f32 %0, %1;" : "=f"(rr) : "f"(1.f + e));
            acc = fmaf(esw[h], rr, acc);
        }
        float sc = base + acc - ((j == tgt) ? 1.f : 0.f);
        arow[j] = sc;
        if (sc > best) { best = sc; bj = j; }
    }
    for (int off = 8; off; off >>= 1) {
        float ob = __shfl_xor_sync(0xffffffffu, best, off);
        int   oj = __shfl_xor_sync(0xffffffffu, bj, off);
        if (ob > best || (ob == best && oj < bj)) { best = ob; bj = oj; }
    }
    if (jl == 0) parsed_out[b * 128 + i] = (float)bj;
}

// ---------------- rel scores + argmax (head gather post-projection) ----------------
__global__ void k_rel(const float* __restrict__ lsW, const float* __restrict__ lsb,
                      float* __restrict__ rel_out, float* __restrict__ pred_out) {
    __shared__ float th[100];
    __shared__ float sc[50];
    int m = blockIdx.x, t = threadIdx.x;
    const float* rm = g_scr + OFF_SCOR + (size_t)m * 400 + 200;
    const float* rh = g_scr + OFF_SCOR + (size_t)g_gidx[m] * 400 + 300;
    for (int h = t; h < 100; h += 64) th[h] = tanhf(rm[h] + rh[h]);
    __syncthreads();
    if (t < 50) {
        float acc = lsb[t];
        const float* wr = lsW + t * 100;
#pragma unroll 10
        for (int h = 0; h < 100; h++) acc = fmaf(th[h], wr[h], acc);
        rel_out[(size_t)m * 50 + t] = acc;
        sc[t] = acc;
    }
    __syncthreads();
    if (t == 0) {
        float best = sc[0]; int bl = 0;
        for (int l = 1; l < 50; l++) if (sc[l] > best) { best = sc[l]; bl = l; }
        pred_out[m] = (float)bl;
    }
}

// ---------------- launch ----------------
extern "C" void kernel_launch(void* const* d_in, const int* in_sizes, int n_in,
                              void* d_out, int out_size) {
    const int* wid  = (const int*)d_in[0];
    const int* uid  = (const int*)d_in[1];
    const int* tarc = (const int*)d_in[2];
    const float* wl = (const float*)d_in[3];
    const float* tl = (const float*)d_in[4];
    const float* l0f_Wih = (const float*)d_in[5];
    const float* l0f_Whh = (const float*)d_in[6];
    const float* l0f_b   = (const float*)d_in[7];
    const float* l0b_Wih = (const float*)d_in[8];
    const float* l0b_Whh = (const float*)d_in[9];
    const float* l0b_b   = (const float*)d_in[10];
    const float* l1f_Wih = (const float*)d_in[11];
    const float* l1f_Whh = (const float*)d_in[12];
    const float* l1f_b   = (const float*)d_in[13];
    const float* l1b_Wih = (const float*)d_in[14];
    const float* l1b_Whh = (const float*)d_in[15];
    const float* l1b_b   = (const float*)d_in[16];
    const float* ehW = (const float*)d_in[17];
    const float* ehb = (const float*)d_in[18];
    const float* emW = (const float*)d_in[19];
    const float* emb = (const float*)d_in[20];
    const float* esW = (const float*)d_in[21];
    const float* esb = (const float*)d_in[22];
    const float* lhW = (const float*)d_in[23];
    const float* lhb = (const float*)d_in[24];
    const float* lmW = (const float*)d_in[25];
    const float* lmb = (const float*)d_in[26];
    const float* lsW = (const float*)d_in[27];
    const float* lsb = (const float*)d_in[28];
    float* out = (float*)d_out;

    float* scr = nullptr;
    cudaGetSymbolAddress((void**)&scr, g_scr);
    float* WORDS = scr + OFF_WORDS;
    float* XG0F = scr + OFF_XG0F;
    float* XG0B = scr + OFF_XG0B;
    float* XG1F = scr + OFF_XG1F;
    float* XG1B = scr + OFF_XG1B;
    float* H0   = scr + OFF_H0;
    float* WE1  = scr + OFF_WE1;
    float* SCOR = scr + OFF_SCOR;
    float* WIH0 = scr + OFF_WIH0;
    float* WIH1 = scr + OFF_WIH1;
    float* SW   = scr + OFF_SW;
    float* B0   = scr + OFF_B0;
    float* B1   = scr + OFF_B1;
    float* SB   = scr + OFF_SB;

    k_prep<<<2202, 256>>>(tarc, l0f_Wih, l0b_Wih, l1f_Wih, l1b_Wih,
                          ehW, emW, lmW, lhW,
                          l0f_b, l0b_b, l1f_b, l1b_b, ehb, emb, lmb, lhb);
    k_embed<<<4096, 128>>>(wid, uid, wl, tl);

    k_gemm<<<dim3(8, 64, 2), 256>>>(WORDS, WIH0, B0, XG0F, 500, 128,
                                    512 * 128, 512, 2048000LL);
    k_scan<<<128, 256>>>(XG0F, XG0B, l0f_Whh, l0b_Whh, H0);
    k_gemm<<<dim3(8, 64, 2), 256>>>(H0, WIH1, B1, XG1F, 500, 256,
                                    512 * 256, 512, 2048000LL);
    k_scan<<<128, 256>>>(XG1F, XG1B, l1f_Whh, l1b_Whh, WE1);
    k_gemm<<<dim3(7, 64, 1), 256>>>(WE1, SW, SB, SCOR, 400, 256, 0, 0, 0LL);

    cudaFuncSetAttribute(k_arc, cudaFuncAttributeMaxDynamicSharedMemorySize, 60000);
    k_arc<<<dim3(8, 32), 256, 58656>>>(esW, esb, out + 8192, out);
    k_rel<<<4096, 64>>>(lsW, lsb, out + 532480, out + 4096);
}